// round 13
// baseline (speedup 1.0000x reference)
#include <cuda_runtime.h>
#include <cuda_fp16.h>
#include <cuda_bf16.h>
#include <cstdint>

#define D 1024
#define NLIN 15
#define MROWS 8192
#define RANK 32
#define BM 128
#define BN 128
#define BK 32
#define NT (D / BK)   // 32 k-tiles
#define SSTR 40       // smem row stride in halves (80B): LDSM-conflict-free, 16B-aligned rows
#define KSPLIT 4
#define BML 64        // lora_t rows per block

// ---------------- device scratch: 52MB total ----------------
__device__ __half g_r1h[MROWS * D];              // relu(lin0) f16
__device__ __half g_r2h[MROWS * D];              // relu(lin1) f16
__device__ __half g_hh [MROWS * D];              // post-LN h f16 (main path reads)
__device__ float  g_tp[KSPLIT * MROWS * RANK];   // lora t partials (K-split)
__device__ int    g_flags[4];                    // 0: lora swap, 1: ln swap, 2/3: dtypes

__device__ __forceinline__ float gld(const float* p, size_t i, size_t n) {
    return (i < n) ? p[i] : 0.f;
}
__device__ __forceinline__ __half fetch_h(const void* p, size_t i, size_t n, int fl) {
    if (i >= n) return __float2half(0.f);
    if (fl == 2) return __float2half(((const float*)p)[i]);
    if (fl == 1) return __float2half(__bfloat162float(((const __nv_bfloat16*)p)[i]));
    return ((const __half*)p)[i];
}
__device__ __forceinline__ float xfetch(int sel, const float* x, size_t nX,
                                        const float* out, size_t gi) {
    switch (sel) {
        case 1:  return __half2float(g_r1h[gi]);
        case 2:  return __half2float(g_r2h[gi]);
        case 3:  return __half2float(g_hh[gi]);
        case 0:  return out[gi];
        default: return (gi < nX) ? x[gi] : 0.f;
    }
}

// ---------------- mma / ldmatrix ----------------
__device__ __forceinline__ void mma16816(float* d, const uint32_t* a, const uint32_t* b) {
    asm volatile(
        "mma.sync.aligned.m16n8k16.row.col.f32.f16.f16.f32 "
        "{%0,%1,%2,%3}, {%4,%5,%6,%7}, {%8,%9}, {%0,%1,%2,%3};\n"
        : "+f"(d[0]), "+f"(d[1]), "+f"(d[2]), "+f"(d[3])
        : "r"(a[0]), "r"(a[1]), "r"(a[2]), "r"(a[3]), "r"(b[0]), "r"(b[1]));
}
__device__ __forceinline__ void ldsm4(uint32_t& r0, uint32_t& r1, uint32_t& r2,
                                      uint32_t& r3, uint32_t addr) {
    asm volatile("ldmatrix.sync.aligned.m8n8.x4.shared.b16 {%0,%1,%2,%3}, [%4];\n"
                 : "=r"(r0), "=r"(r1), "=r"(r2), "=r"(r3) : "r"(addr));
}

// ---------------- diagnostic fill ----------------
__global__ void diag_kernel(float* out, long long n, float val) {
    long long i = (long long)blockIdx.x * blockDim.x + threadIdx.x;
    if (i < n) out[i] = val;
}

// ---------------- probe (unchanged) ----------------
__global__ void probe_kernel(const float* __restrict__ a1, const float* __restrict__ a2,
                             const float* __restrict__ g1, const float* __restrict__ g2,
                             const void* __restrict__ sc, const void* __restrict__ bi) {
    int lane = threadIdx.x;
    float s1 = 0.f, s2 = 0.f;
    for (int i = lane; i < 4096; i += 32) { s1 += fabsf(a1[i]); s2 += fabsf(a2[i]); }
#pragma unroll
    for (int o = 16; o; o >>= 1) {
        s1 += __shfl_xor_sync(0xffffffffu, s1, o);
        s2 += __shfl_xor_sync(0xffffffffu, s2, o);
    }
    float t1 = 0.f, t2 = 0.f;
    for (int i = lane; i < 1024; i += 32) { t1 += fabsf(g1[i]); t2 += fabsf(g2[i]); }
#pragma unroll
    for (int o = 16; o; o >>= 1) {
        t1 += __shfl_xor_sync(0xffffffffu, t1, o);
        t2 += __shfl_xor_sync(0xffffffffu, t2, o);
    }
    if (lane == 0) {
        g_flags[0] = (s1 < s2) ? 1 : 0;
        g_flags[1] = (t1 < t2) ? 1 : 0;
        {
            const __half* h = (const __half*)sc;
            const __nv_bfloat16* b = (const __nv_bfloat16*)sc;
            const float* f = (const float*)sc;
            int c16 = 0, cbf = 0, c32 = 0;
            for (int i = 0; i < 256; i++) {
                float v = __half2float(h[i]);
                if (isfinite(v) && v > 0.004f && v < 0.3f) c16++;
                float vb = __bfloat162float(b[i]);
                if (isfinite(vb) && vb > 0.004f && vb < 0.3f) cbf++;
                float vf = f[i];
                if (isfinite(vf) && vf > 0.004f && vf < 0.3f) c32++;
            }
            int fl = 0, best = c16;
            if (cbf > best) { fl = 1; best = cbf; }
            if (c32 > best) { fl = 2; }
            g_flags[2] = fl;
        }
        {
            const __half* h = (const __half*)bi;
            const __nv_bfloat16* b = (const __nv_bfloat16*)bi;
            const float* f = (const float*)bi;
            int c16 = 0, cbf = 0, c32 = 0;
            for (int i = 0; i < 256; i++) {
                float v = __half2float(h[i]);
                if (isfinite(v) && fabsf(v) < 0.5f) c16++;
                float vb = __bfloat162float(b[i]);
                if (isfinite(vb) && fabsf(vb) < 0.5f) cbf++;
                float vf = f[i];
                if (isfinite(vf) && fabsf(vf) < 0.5f) c32++;
            }
            int fl = 0, best = c16;
            if (cbf > best) { fl = 1; best = cbf; }
            if (c32 > best) { fl = 2; }
            g_flags[3] = fl;
        }
    }
}

// ---------------- lora t partials: 64-row blocks, 128 threads, K-split ----------------
// grid (MROWS/BML, KSPLIT)
__global__ __launch_bounds__(128) void lora_t_kernel(const float* x, int xsel, int nX,
                                                     const float* out,
                                                     const float* __restrict__ Ac1,
                                                     const float* __restrict__ Ac2,
                                                     int li) {
    int lc = (li > NLIN - 1) ? (NLIN - 1) : li;   // JAX clamp semantics
    const float* Abase = g_flags[0] ? Ac2 : Ac1;
    size_t aoff = (size_t)lc * RANK * D;
    __shared__ __half sA[BML][SSTR];
    __shared__ __half sW[RANK][SSTR];
    int tid = threadIdx.x;
    int wid = tid >> 5, lane = tid & 31;
    int gid = lane >> 2, tig = lane & 3;
    int m0 = blockIdx.x * BML;
    int ks = blockIdx.y;

    float acc[4][4];
#pragma unroll
    for (int ni = 0; ni < 4; ni++)
#pragma unroll
        for (int j = 0; j < 4; j++) acc[ni][j] = 0.f;

    for (int kt = 0; kt < NT / KSPLIT; ++kt) {
        int k0 = ks * (D / KSPLIT) + kt * BK;
#pragma unroll
        for (int i = 0; i < 16; i++) {              // X tile 64x32
            int e = tid + i * 128;
            int r = e >> 5, c = e & 31;
            sA[r][c] = __float2half(xfetch(xsel, x, (size_t)nX, out,
                                           (size_t)(m0 + r) * D + k0 + c));
        }
#pragma unroll
        for (int i = 0; i < 8; i++) {               // A tile 32x32
            int e = tid + i * 128;
            int r = e >> 5, c = e & 31;
            sW[r][c] = __float2half(Abase[aoff + (size_t)r * D + k0 + c]);
        }
        __syncthreads();
#pragma unroll
        for (int kk = 0; kk < 2; kk++) {
            int kb = kk * 16;
            uint32_t af[4];
            int rb = wid * 16;
            af[0] = *(const uint32_t*)&sA[rb + gid][kb + tig * 2];
            af[1] = *(const uint32_t*)&sA[rb + gid + 8][kb + tig * 2];
            af[2] = *(const uint32_t*)&sA[rb + gid][kb + tig * 2 + 8];
            af[3] = *(const uint32_t*)&sA[rb + gid + 8][kb + tig * 2 + 8];
#pragma unroll
            for (int ni = 0; ni < 4; ni++) {
                uint32_t bf[2];
                bf[0] = *(const uint32_t*)&sW[ni * 8 + gid][kb + tig * 2];
                bf[1] = *(const uint32_t*)&sW[ni * 8 + gid][kb + tig * 2 + 8];
                mma16816(acc[ni], af, bf);
            }
        }
        __syncthreads();
    }
    float* tp = g_tp + (size_t)ks * MROWS * RANK;
#pragma unroll
    for (int ni = 0; ni < 4; ni++) {
        int r0 = m0 + wid * 16 + gid;
        int c0 = ni * 8 + tig * 2;
        tp[(size_t)r0 * RANK + c0]           = acc[ni][0];
        tp[(size_t)r0 * RANK + c0 + 1]       = acc[ni][1];
        tp[(size_t)(r0 + 8) * RANK + c0]     = acc[ni][2];
        tp[(size_t)(r0 + 8) * RANK + c0 + 1] = acc[ni][3];
    }
}

// ---------------- fused QLoRA linear: double-buffered + LDSM fragments ----------------
// XK: 0 = f32 via xf32 ptr; 1 = g_r1h; 2 = g_r2h; 3 = g_hh.
template <int XK, bool RELU, bool RESID>
__global__ __launch_bounds__(256) void gemm_kernel(
    const float* __restrict__ xf32,
    float* __restrict__ out, long long nOut, int ysel,
    const int* __restrict__ q,
    const void* __restrict__ sc, int ns,
    const void* __restrict__ biases, int nbias, int li,
    const float* __restrict__ Bc1, const float* __restrict__ Bc2,
    const float* __restrict__ resf32) {
    int lc = (li > NLIN - 1) ? (NLIN - 1) : li;   // JAX clamp semantics
    const float* Blbase = g_flags[0] ? Bc1 : Bc2;
    size_t bloff = (size_t)lc * D * RANK;

    __shared__ __half sA[2][BM][SSTR];
    __shared__ __half sB[2][BN][SSTR];

    int tid = threadIdx.x;
    int wid = tid >> 5, lane = tid & 31;
    int gid = lane >> 2, tig = lane & 3;
    int wm = wid & 3, wn = wid >> 2;
    int m0 = blockIdx.y * BM, n0 = blockIdx.x * BN;
    int scfl = g_flags[2];

    const __half c215 = __float2half(2.0f / 15.0f);
    const __half hone = __float2half(1.0f);

    // LDSM per-lane address offsets (bytes), relative to buffer base
    uint32_t sAu = (uint32_t)__cvta_generic_to_shared(&sA[0][0][0]);
    uint32_t sBu = (uint32_t)__cvta_generic_to_shared(&sB[0][0][0]);
    const uint32_t BUFB = BM * SSTR * 2;   // 10240 bytes per buffer
    // A: matrices (rb,kb),(rb+8,kb),(rb,kb+8),(rb+8,kb+8); rb = wm*32 + mi*16
    uint32_t a_off = (uint32_t)(((wm * 32 + (lane & 15)) * SSTR + ((lane >> 4) * 8)) * 2);
    // B: pair p base nb = wn*64 + p*16; matrices (nb,kb),(nb,kb+8),(nb+8,kb),(nb+8,kb+8)
    uint32_t b_off = (uint32_t)(((wn * 64 + (lane & 7) + ((lane & 16) ? 8 : 0)) * SSTR
                                 + ((lane & 8) ? 8 : 0)) * 2);

    float acc[2][8][4];
#pragma unroll
    for (int mi = 0; mi < 2; mi++)
#pragma unroll
        for (int ni = 0; ni < 8; ni++)
#pragma unroll
            for (int j = 0; j < 4; j++) acc[mi][ni][j] = 0.f;

    // staging registers
    float4 ar[4];
    int4   ah[2];
    int4   br[4];
    __half scv;
    int dq_row = tid >> 1, dq_g = tid & 1;

    auto ldA = [&](int kt) {
        int k0 = kt * BK;
        if (XK == 0) {
#pragma unroll
            for (int i = 0; i < 4; i++) {
                int e = tid + i * 256;
                int r = e >> 3, c4 = e & 7;
                ar[i] = *(const float4*)(xf32 + (size_t)(m0 + r) * D + k0 + c4 * 4);
            }
        } else {
            const __half* src = (XK == 1) ? g_r1h : ((XK == 2) ? g_r2h : g_hh);
#pragma unroll
            for (int i = 0; i < 2; i++) {
                int e = tid + i * 256;
                int r = e >> 2, c8 = e & 3;
                ah[i] = *(const int4*)(src + (size_t)(m0 + r) * D + k0 + c8 * 8);
            }
        }
    };
    auto stA = [&](int b) {
        if (XK == 0) {
#pragma unroll
            for (int i = 0; i < 4; i++) {
                int e = tid + i * 256;
                int r = e >> 3, c4 = e & 7;
                __half2* d = (__half2*)&sA[b][r][c4 * 4];
                d[0] = __floats2half2_rn(ar[i].x, ar[i].y);
                d[1] = __floats2half2_rn(ar[i].z, ar[i].w);
            }
        } else {
#pragma unroll
            for (int i = 0; i < 2; i++) {
                int e = tid + i * 256;
                int r = e >> 2, c8 = e & 3;
                *(int4*)&sA[b][r][c8 * 8] = ah[i];
            }
        }
    };
    auto ldB = [&](int kt) {
        int k0 = kt * BK;
        int row = n0 + dq_row;
        int colb = k0 + dq_g * 16;
        const int* qp = q + (size_t)lc * D * D + (size_t)row * D + colb;
#pragma unroll
        for (int i = 0; i < 4; i++) br[i] = *(const int4*)(qp + i * 4);
        scv = fetch_h(sc, (size_t)lc * D * (D / 16) + (size_t)row * (D / 16) + (colb >> 4),
                      (size_t)ns, scfl);
    };
    auto stB = [&](int b) {
#pragma unroll
        for (int v = 0; v < 4; v++) {
            __half w0 = __hmul(__hsub(__hmul(__int2half_rn(br[v].x), c215), hone), scv);
            __half w1 = __hmul(__hsub(__hmul(__int2half_rn(br[v].y), c215), hone), scv);
            __half w2 = __hmul(__hsub(__hmul(__int2half_rn(br[v].z), c215), hone), scv);
            __half w3 = __hmul(__hsub(__hmul(__int2half_rn(br[v].w), c215), hone), scv);
            int cb = dq_g * 16 + v * 4;
            *(__half2*)&sB[b][dq_row][cb]     = __halves2half2(w0, w1);
            *(__half2*)&sB[b][dq_row][cb + 2] = __halves2half2(w2, w3);
        }
    };

    // prologue
    ldA(0); ldB(0); stA(0); stB(0);
    __syncthreads();

    for (int kt = 0; kt < NT; ++kt) {
        int cur = kt & 1;
        uint32_t abase = sAu + cur * BUFB + a_off;
        uint32_t bbase = sBu + cur * BUFB + b_off;
        if (kt + 1 < NT) { ldA(kt + 1); ldB(kt + 1); }
#pragma unroll
        for (int kk = 0; kk < 2; kk++) {
            uint32_t kbyte = kk * 32;   // 16 halves
            uint32_t af[2][4], bf[8][2];
#pragma unroll
            for (int mi = 0; mi < 2; mi++)
                ldsm4(af[mi][0], af[mi][1], af[mi][2], af[mi][3],
                      abase + mi * (16 * SSTR * 2) + kbyte);
#pragma unroll
            for (int p = 0; p < 4; p++)
                ldsm4(bf[2 * p][0], bf[2 * p][1], bf[2 * p + 1][0], bf[2 * p + 1][1],
                      bbase + p * (16 * SSTR * 2) + kbyte);
#pragma unroll
            for (int mi = 0; mi < 2; mi++)
#pragma unroll
                for (int ni = 0; ni < 8; ni++) mma16816(acc[mi][ni], af[mi], bf[ni]);
        }
        if (kt + 1 < NT) { stA(cur ^ 1); stB(cur ^ 1); }
        __syncthreads();
    }

    // f16-round + f16 bias (reference numerics), widen to f32
    {
        int fl = g_flags[3];
#pragma unroll
        for (int ni = 0; ni < 8; ni++) {
            int c0 = n0 + wn * 64 + ni * 8 + tig * 2;
            __half b0 = fetch_h(biases, (size_t)lc * D + c0, (size_t)nbias, fl);
            __half b1 = fetch_h(biases, (size_t)lc * D + c0 + 1, (size_t)nbias, fl);
#pragma unroll
            for (int mi = 0; mi < 2; mi++) {
                acc[mi][ni][0] = __half2float(__hadd(__float2half(acc[mi][ni][0]), b0));
                acc[mi][ni][1] = __half2float(__hadd(__float2half(acc[mi][ni][1]), b1));
                acc[mi][ni][2] = __half2float(__hadd(__float2half(acc[mi][ni][2]), b0));
                acc[mi][ni][3] = __half2float(__hadd(__float2half(acc[mi][ni][3]), b1));
            }
        }
    }

    // LoRA as 2 extra MMA k-steps: sA[0] <- sum of t partials, sB[0] <- 0.125*Bl
#pragma unroll
    for (int i = 0; i < 16; i++) {
        int e = tid + i * 256;
        int r = e >> 5, c = e & 31;
        size_t ti = (size_t)(m0 + r) * RANK + c;
        float tv = g_tp[ti] + g_tp[(size_t)MROWS * RANK + ti]
                 + g_tp[2 * (size_t)MROWS * RANK + ti]
                 + g_tp[3 * (size_t)MROWS * RANK + ti];
        sA[0][r][c] = __float2half(tv);
        sB[0][r][c] = __float2half(0.125f * Blbase[bloff + (size_t)(n0 + r) * RANK + c]);
    }
    __syncthreads();
#pragma unroll
    for (int kk = 0; kk < 2; kk++) {
        uint32_t kbyte = kk * 32;
        uint32_t af[2][4], bf[8][2];
#pragma unroll
        for (int mi = 0; mi < 2; mi++)
            ldsm4(af[mi][0], af[mi][1], af[mi][2], af[mi][3],
                  sAu + a_off + mi * (16 * SSTR * 2) + kbyte);
#pragma unroll
        for (int p = 0; p < 4; p++)
            ldsm4(bf[2 * p][0], bf[2 * p][1], bf[2 * p + 1][0], bf[2 * p + 1][1],
                  sBu + b_off + p * (16 * SSTR * 2) + kbyte);
#pragma unroll
        for (int mi = 0; mi < 2; mi++)
#pragma unroll
            for (int ni = 0; ni < 8; ni++) mma16816(acc[mi][ni], af[mi], bf[ni]);
    }

    // epilogue: residual / relu / store
#pragma unroll
    for (int mi = 0; mi < 2; mi++)
#pragma unroll
        for (int ni = 0; ni < 8; ni++) {
            int r0 = m0 + wm * 32 + mi * 16 + gid;
            int c0 = n0 + wn * 64 + ni * 8 + tig * 2;
#pragma unroll
            for (int h = 0; h < 2; h++) {
                int m = r0 + h * 8;
                float v0 = acc[mi][ni][h * 2], v1 = acc[mi][ni][h * 2 + 1];
                size_t gi = (size_t)m * D + c0;
                if (RESID) { v0 += resf32[gi]; v1 += resf32[gi + 1]; }
                if (RELU)  { v0 = fmaxf(v0, 0.f); v1 = fmaxf(v1, 0.f); }
                if (ysel == 1) {
                    g_r1h[gi] = __float2half(v0); g_r1h[gi + 1] = __float2half(v1);
                } else if (ysel == 2) {
                    g_r2h[gi] = __float2half(v0); g_r2h[gi + 1] = __float2half(v1);
                } else if ((long long)gi + 1 < nOut) {
                    out[gi] = v0; out[gi + 1] = v1;
                }
            }
        }
}

// ---------------- layernorm: in-place f32 + f16 copy for the main path ----------------
__global__ __launch_bounds__(256) void ln_kernel(float* out, long long nOut,
                                                 const float* __restrict__ gc1,
                                                 const float* __restrict__ gc2, int ng,
                                                 int blk) {
    const float* gbase = g_flags[1] ? gc2 : gc1;
    const float* bbase = g_flags[1] ? gc1 : gc2;
    int row = blockIdx.x * 8 + (threadIdx.x >> 5);
    int lane = threadIdx.x & 31;
    float v[32];
    float s = 0.f;
#pragma unroll
    for (int i = 0; i < 32; i++) {
        size_t gi = (size_t)row * D + lane + i * 32;
        v[i] = ((long long)gi < nOut) ? out[gi] : 0.f;
        s += v[i];
    }
#pragma unroll
    for (int off = 16; off > 0; off >>= 1) s += __shfl_xor_sync(0xffffffffu, s, off);
    float mu = s * (1.f / D);
    float ss = 0.f;
#pragma unroll
    for (int i = 0; i < 32; i++) { float d = v[i] - mu; ss += d * d; }
#pragma unroll
    for (int off = 16; off > 0; off >>= 1) ss += __shfl_xor_sync(0xffffffffu, ss, off);
    float inv = rsqrtf(ss * (1.f / D) + 1e-5f);
#pragma unroll
    for (int i = 0; i < 32; i++) {
        int c = lane + i * 32;
        size_t pi = (size_t)blk * D + c;
        float gg = gld(gbase, pi, (size_t)ng);
        float bb = gld(bbase, pi, (size_t)ng);
        size_t gi = (size_t)row * D + c;
        float y = (v[i] - mu) * inv * gg + bb;
        if ((long long)gi < nOut) out[gi] = y;
        g_hh[gi] = __float2half(y);
    }
}

// ---------------- host launch ----------------
extern "C" void kernel_launch(void* const* d_in, const int* in_sizes, int n_in,
                              void* d_out, int out_size) {
    float* out = (float*)d_out;

    int ix = -1, iq = -1, is_ = -1, ib = -1, iA = -1, iB = -1, ig = -1, ib2 = -1;
    for (int i = 0; i < n_in; i++) {
        int sz = in_sizes[i];
        if      (sz == 8388608)  { if (ix < 0) ix = i; }
        else if (sz == 15728640) { if (iq < 0) iq = i; }
        else if (sz == 983040)   { if (is_ < 0) is_ = i; }
        else if (sz == 15360)    { if (ib < 0) ib = i; }
        else if (sz == 491520)   { if (iA < 0) iA = i; else if (iB < 0) iB = i; }
        else if (sz == 5120)     { if (ig < 0) ig = i; else if (ib2 < 0) ib2 = i; }
    }
    bool ok = (n_in >= 8) && ix >= 0 && iq >= 0 && is_ >= 0 && ib >= 0 &&
              iA >= 0 && iB >= 0 && ig >= 0 && ib2 >= 0;
    if (!ok) {
        int mask = (ix >= 0 ? 1 : 0) | (iq >= 0 ? 2 : 0) | (is_ >= 0 ? 4 : 0) |
                   (ib >= 0 ? 8 : 0) | ((iA >= 0 && iB >= 0) ? 16 : 0) |
                   ((ig >= 0 && ib2 >= 0) ? 32 : 0);
        float val = 1.0e6f * (float)n_in + 1000.0f * (float)mask;
        long long n = out_size;
        if (n > 8388608LL) n = 8388608LL;
        diag_kernel<<<(int)((n + 255) / 256), 256>>>(out, n, val);
        return;
    }

    const float* x      = (const float*)d_in[ix];
    const int*   qw     = (const int*)d_in[iq];
    const void*  scales = d_in[is_];
    const void*  biases = d_in[ib];
    const float* lA1    = (const float*)d_in[iA];
    const float* lA2    = (const float*)d_in[iB];
    const float* lg1    = (const float*)d_in[ig];
    const float* lg2    = (const float*)d_in[ib2];
    int nx = in_sizes[ix], ns = in_sizes[is_], nb = in_sizes[ib];
    int ng = in_sizes[ig];
    long long nOut = out_size;

    probe_kernel<<<1, 32>>>(lA1, lA2, lg1, lg2, scales, biases);

    dim3 ggrid(D / BN, MROWS / BM);      // (8, 64)
    dim3 lgrid(MROWS / BML, KSPLIT);     // (128, 4)

    int li = 0;
    for (int blk = 0; blk < 6; blk++) {
        // linear 0 (+relu): h -> r1h (f16). blk0 reads f32 x; later blocks read f16 g_hh.
        if (blk == 0) {
            lora_t_kernel<<<lgrid, 128>>>(x, -1, nx, out, lA1, lA2, li);
            gemm_kernel<0, true, false><<<ggrid, 256>>>(x, out, nOut, 1,
                                                        qw, scales, ns, biases, nb, li,
                                                        lA1, lA2, nullptr);
        } else {
            lora_t_kernel<<<lgrid, 128>>>(x, 3, nx, out, lA1, lA2, li);
            gemm_kernel<3, true, false><<<ggrid, 256>>>(nullptr, out, nOut, 1,
                                                        qw, scales, ns, biases, nb, li,
                                                        lA1, lA2, nullptr);
        }
        li++;
        // linear 1 (+relu): r1h -> r2h (f16)
        lora_t_kernel<<<lgrid, 128>>>(x, 1, nx, out, lA1, lA2, li);
        gemm_kernel<1, true, false><<<ggrid, 256>>>(nullptr, out, nOut, 2,
                                                    qw, scales, ns, biases, nb, li,
                                                    lA1, lA2, nullptr);
        li++;
        // linear 2 (+block residual): r2h -> d_out; resid = f32 stream (x or out)
        const float* hptr = (blk == 0) ? x : out;
        lora_t_kernel<<<lgrid, 128>>>(x, 2, nx, out, lA1, lA2, li);
        gemm_kernel<2, false, true><<<ggrid, 256>>>(nullptr, out, nOut, 0,
                                                    qw, scales, ns, biases, nb, li,
                                                    lA1, lA2, hptr);
        li++;
        if (blk < 5) {
            ln_kernel<<<MROWS / 8, 256>>>(out, nOut, lg1, lg2, ng, blk);
        }
    }
}

// round 14
// speedup vs baseline: 1.1011x; 1.1011x over previous
#include <cuda_runtime.h>
#include <cuda_fp16.h>
#include <cuda_bf16.h>
#include <cstdint>

#define D 1024
#define NLIN 15
#define MROWS 8192
#define RANK 32
#define BM 128
#define BN 128
#define BK 32
#define NT (D / BK)   // 32 k-tiles
#define SSTR 40       // smem row stride in halves (80B): conflict-free frag LDS
#define KSPLIT 8

// ---------------- device scratch: 56MB total ----------------
__device__ __half g_r1h[MROWS * D];              // relu(lin0) f16
__device__ __half g_r2h[MROWS * D];              // relu(lin1) f16
__device__ __half g_hh [MROWS * D];              // post-LN h f16 (main path reads)
__device__ float  g_tp[KSPLIT * MROWS * RANK];   // lora t partials (K-split)
__device__ int    g_flags[4];                    // 0: lora swap, 1: ln swap, 2/3: dtypes

__device__ __forceinline__ float gld(const float* p, size_t i, size_t n) {
    return (i < n) ? p[i] : 0.f;
}
__device__ __forceinline__ __half fetch_h(const void* p, size_t i, size_t n, int fl) {
    if (i >= n) return __float2half(0.f);
    if (fl == 2) return __float2half(((const float*)p)[i]);
    if (fl == 1) return __float2half(__bfloat162float(((const __nv_bfloat16*)p)[i]));
    return ((const __half*)p)[i];
}
__device__ __forceinline__ float xfetch(int sel, const float* x, size_t nX,
                                        const float* out, size_t gi) {
    switch (sel) {
        case 1:  return __half2float(g_r1h[gi]);
        case 2:  return __half2float(g_r2h[gi]);
        case 3:  return __half2float(g_hh[gi]);
        case 0:  return out[gi];
        default: return (gi < nX) ? x[gi] : 0.f;
    }
}

// ---------------- mma.sync m16n8k16 f16*f16 -> f32 ----------------
__device__ __forceinline__ void mma16816(float* d, const uint32_t* a, const uint32_t* b) {
    asm volatile(
        "mma.sync.aligned.m16n8k16.row.col.f32.f16.f16.f32 "
        "{%0,%1,%2,%3}, {%4,%5,%6,%7}, {%8,%9}, {%0,%1,%2,%3};\n"
        : "+f"(d[0]), "+f"(d[1]), "+f"(d[2]), "+f"(d[3])
        : "r"(a[0]), "r"(a[1]), "r"(a[2]), "r"(a[3]), "r"(b[0]), "r"(b[1]));
}

// ---------------- diagnostic fill ----------------
__global__ void diag_kernel(float* out, long long n, float val) {
    long long i = (long long)blockIdx.x * blockDim.x + threadIdx.x;
    if (i < n) out[i] = val;
}

// ---------------- probe (unchanged) ----------------
__global__ void probe_kernel(const float* __restrict__ a1, const float* __restrict__ a2,
                             const float* __restrict__ g1, const float* __restrict__ g2,
                             const void* __restrict__ sc, const void* __restrict__ bi) {
    int lane = threadIdx.x;
    float s1 = 0.f, s2 = 0.f;
    for (int i = lane; i < 4096; i += 32) { s1 += fabsf(a1[i]); s2 += fabsf(a2[i]); }
#pragma unroll
    for (int o = 16; o; o >>= 1) {
        s1 += __shfl_xor_sync(0xffffffffu, s1, o);
        s2 += __shfl_xor_sync(0xffffffffu, s2, o);
    }
    float t1 = 0.f, t2 = 0.f;
    for (int i = lane; i < 1024; i += 32) { t1 += fabsf(g1[i]); t2 += fabsf(g2[i]); }
#pragma unroll
    for (int o = 16; o; o >>= 1) {
        t1 += __shfl_xor_sync(0xffffffffu, t1, o);
        t2 += __shfl_xor_sync(0xffffffffu, t2, o);
    }
    if (lane == 0) {
        g_flags[0] = (s1 < s2) ? 1 : 0;
        g_flags[1] = (t1 < t2) ? 1 : 0;
        {
            const __half* h = (const __half*)sc;
            const __nv_bfloat16* b = (const __nv_bfloat16*)sc;
            const float* f = (const float*)sc;
            int c16 = 0, cbf = 0, c32 = 0;
            for (int i = 0; i < 256; i++) {
                float v = __half2float(h[i]);
                if (isfinite(v) && v > 0.004f && v < 0.3f) c16++;
                float vb = __bfloat162float(b[i]);
                if (isfinite(vb) && vb > 0.004f && vb < 0.3f) cbf++;
                float vf = f[i];
                if (isfinite(vf) && vf > 0.004f && vf < 0.3f) c32++;
            }
            int fl = 0, best = c16;
            if (cbf > best) { fl = 1; best = cbf; }
            if (c32 > best) { fl = 2; }
            g_flags[2] = fl;
        }
        {
            const __half* h = (const __half*)bi;
            const __nv_bfloat16* b = (const __nv_bfloat16*)bi;
            const float* f = (const float*)bi;
            int c16 = 0, cbf = 0, c32 = 0;
            for (int i = 0; i < 256; i++) {
                float v = __half2float(h[i]);
                if (isfinite(v) && fabsf(v) < 0.5f) c16++;
                float vb = __bfloat162float(b[i]);
                if (isfinite(vb) && fabsf(vb) < 0.5f) cbf++;
                float vf = f[i];
                if (isfinite(vf) && fabsf(vf) < 0.5f) c32++;
            }
            int fl = 0, best = c16;
            if (cbf > best) { fl = 1; best = cbf; }
            if (c32 > best) { fl = 2; }
            g_flags[3] = fl;
        }
    }
}

// ---------------- lora t partials: R12 shape (128 rows, 256 thr), K-split 8 ----------------
// grid (MROWS/BM, KSPLIT); each block: 128 rows x RANK over a 128-wide K chunk.
__global__ __launch_bounds__(256) void lora_t_kernel(const float* x, int xsel, int nX,
                                                     const float* out,
                                                     const float* __restrict__ Ac1,
                                                     const float* __restrict__ Ac2,
                                                     int li) {
    int lc = (li > NLIN - 1) ? (NLIN - 1) : li;   // JAX clamp semantics
    const float* Abase = g_flags[0] ? Ac2 : Ac1;
    size_t aoff = (size_t)lc * RANK * D;
    __shared__ __half sA[BM][SSTR];
    __shared__ __half sW[RANK][SSTR];
    int tid = threadIdx.x;
    int wid = tid >> 5, lane = tid & 31;
    int gid = lane >> 2, tig = lane & 3;
    int m0 = blockIdx.x * BM;
    int ks = blockIdx.y;

    float acc[4][4];
#pragma unroll
    for (int ni = 0; ni < 4; ni++)
#pragma unroll
        for (int j = 0; j < 4; j++) acc[ni][j] = 0.f;

    for (int kt = 0; kt < NT / KSPLIT; ++kt) {
        int k0 = ks * (D / KSPLIT) + kt * BK;
#pragma unroll
        for (int i = 0; i < 16; i++) {
            int e = tid + i * 256;
            int r = e >> 5, c = e & 31;
            sA[r][c] = __float2half(xfetch(xsel, x, (size_t)nX, out,
                                           (size_t)(m0 + r) * D + k0 + c));
        }
#pragma unroll
        for (int i = 0; i < 4; i++) {
            int e = tid + i * 256;
            int r = e >> 5, c = e & 31;
            sW[r][c] = __float2half(Abase[aoff + (size_t)r * D + k0 + c]);
        }
        __syncthreads();
#pragma unroll
        for (int kk = 0; kk < 2; kk++) {
            int kb = kk * 16;
            uint32_t af[4];
            int rb = wid * 16;
            af[0] = *(const uint32_t*)&sA[rb + gid][kb + tig * 2];
            af[1] = *(const uint32_t*)&sA[rb + gid + 8][kb + tig * 2];
            af[2] = *(const uint32_t*)&sA[rb + gid][kb + tig * 2 + 8];
            af[3] = *(const uint32_t*)&sA[rb + gid + 8][kb + tig * 2 + 8];
#pragma unroll
            for (int ni = 0; ni < 4; ni++) {
                uint32_t bf[2];
                bf[0] = *(const uint32_t*)&sW[ni * 8 + gid][kb + tig * 2];
                bf[1] = *(const uint32_t*)&sW[ni * 8 + gid][kb + tig * 2 + 8];
                mma16816(acc[ni], af, bf);
            }
        }
        __syncthreads();
    }
    float* tp = g_tp + (size_t)ks * MROWS * RANK;
#pragma unroll
    for (int ni = 0; ni < 4; ni++) {
        int r0 = m0 + wid * 16 + gid;
        int c0 = ni * 8 + tig * 2;
        tp[(size_t)r0 * RANK + c0]           = acc[ni][0];
        tp[(size_t)r0 * RANK + c0 + 1]       = acc[ni][1];
        tp[(size_t)(r0 + 8) * RANK + c0]     = acc[ni][2];
        tp[(size_t)(r0 + 8) * RANK + c0 + 1] = acc[ni][3];
    }
}

// ---------------- fused QLoRA linear: R12 mainloop (double-buffered, scalar LDS frags) ----
// XK: 0 = f32 via xf32 ptr; 1 = g_r1h; 2 = g_r2h; 3 = g_hh.
template <int XK, bool RELU, bool RESID>
__global__ __launch_bounds__(256) void gemm_kernel(
    const float* __restrict__ xf32,
    float* __restrict__ out, long long nOut, int ysel,
    const int* __restrict__ q,
    const void* __restrict__ sc, int ns,
    const void* __restrict__ biases, int nbias, int li,
    const float* __restrict__ Bc1, const float* __restrict__ Bc2,
    const float* __restrict__ resf32) {
    int lc = (li > NLIN - 1) ? (NLIN - 1) : li;   // JAX clamp semantics
    const float* Blbase = g_flags[0] ? Bc1 : Bc2;
    size_t bloff = (size_t)lc * D * RANK;

    __shared__ __half sA[2][BM][SSTR];
    __shared__ __half sB[2][BN][SSTR];

    int tid = threadIdx.x;
    int wid = tid >> 5, lane = tid & 31;
    int gid = lane >> 2, tig = lane & 3;
    int wm = wid & 3, wn = wid >> 2;
    int m0 = blockIdx.y * BM, n0 = blockIdx.x * BN;
    int scfl = g_flags[2];

    const __half c215 = __float2half(2.0f / 15.0f);
    const __half hone = __float2half(1.0f);

    float acc[2][8][4];
#pragma unroll
    for (int mi = 0; mi < 2; mi++)
#pragma unroll
        for (int ni = 0; ni < 8; ni++)
#pragma unroll
            for (int j = 0; j < 4; j++) acc[mi][ni][j] = 0.f;

    // staging registers
    float4 ar[4];
    int4   ah[2];
    int4   br[4];
    __half scv;
    int dq_row = tid >> 1, dq_g = tid & 1;

    auto ldA = [&](int kt) {
        int k0 = kt * BK;
        if (XK == 0) {
#pragma unroll
            for (int i = 0; i < 4; i++) {
                int e = tid + i * 256;
                int r = e >> 3, c4 = e & 7;
                ar[i] = *(const float4*)(xf32 + (size_t)(m0 + r) * D + k0 + c4 * 4);
            }
        } else {
            const __half* src = (XK == 1) ? g_r1h : ((XK == 2) ? g_r2h : g_hh);
#pragma unroll
            for (int i = 0; i < 2; i++) {
                int e = tid + i * 256;
                int r = e >> 2, c8 = e & 3;
                ah[i] = *(const int4*)(src + (size_t)(m0 + r) * D + k0 + c8 * 8);
            }
        }
    };
    auto stA = [&](int b) {
        if (XK == 0) {
#pragma unroll
            for (int i = 0; i < 4; i++) {
                int e = tid + i * 256;
                int r = e >> 3, c4 = e & 7;
                __half2* d = (__half2*)&sA[b][r][c4 * 4];
                d[0] = __floats2half2_rn(ar[i].x, ar[i].y);
                d[1] = __floats2half2_rn(ar[i].z, ar[i].w);
            }
        } else {
#pragma unroll
            for (int i = 0; i < 2; i++) {
                int e = tid + i * 256;
                int r = e >> 2, c8 = e & 3;
                *(int4*)&sA[b][r][c8 * 8] = ah[i];
            }
        }
    };
    auto ldB = [&](int kt) {
        int k0 = kt * BK;
        int row = n0 + dq_row;
        int colb = k0 + dq_g * 16;
        const int* qp = q + (size_t)lc * D * D + (size_t)row * D + colb;
#pragma unroll
        for (int i = 0; i < 4; i++) br[i] = *(const int4*)(qp + i * 4);
        scv = fetch_h(sc, (size_t)lc * D * (D / 16) + (size_t)row * (D / 16) + (colb >> 4),
                      (size_t)ns, scfl);
    };
    auto stB = [&](int b) {
#pragma unroll
        for (int v = 0; v < 4; v++) {
            __half w0 = __hmul(__hsub(__hmul(__int2half_rn(br[v].x), c215), hone), scv);
            __half w1 = __hmul(__hsub(__hmul(__int2half_rn(br[v].y), c215), hone), scv);
            __half w2 = __hmul(__hsub(__hmul(__int2half_rn(br[v].z), c215), hone), scv);
            __half w3 = __hmul(__hsub(__hmul(__int2half_rn(br[v].w), c215), hone), scv);
            int cb = dq_g * 16 + v * 4;
            *(__half2*)&sB[b][dq_row][cb]     = __halves2half2(w0, w1);
            *(__half2*)&sB[b][dq_row][cb + 2] = __halves2half2(w2, w3);
        }
    };

    // prologue
    ldA(0); ldB(0); stA(0); stB(0);
    __syncthreads();

    for (int kt = 0; kt < NT; ++kt) {
        int cur = kt & 1;
        if (kt + 1 < NT) { ldA(kt + 1); ldB(kt + 1); }
#pragma unroll
        for (int kk = 0; kk < 2; kk++) {
            int kb = kk * 16;
            uint32_t af[2][4], bf[8][2];
#pragma unroll
            for (int mi = 0; mi < 2; mi++) {
                int rb = wm * 32 + mi * 16;
                af[mi][0] = *(const uint32_t*)&sA[cur][rb + gid][kb + tig * 2];
                af[mi][1] = *(const uint32_t*)&sA[cur][rb + gid + 8][kb + tig * 2];
                af[mi][2] = *(const uint32_t*)&sA[cur][rb + gid][kb + tig * 2 + 8];
                af[mi][3] = *(const uint32_t*)&sA[cur][rb + gid + 8][kb + tig * 2 + 8];
            }
#pragma unroll
            for (int ni = 0; ni < 8; ni++) {
                int nb = wn * 64 + ni * 8 + gid;
                bf[ni][0] = *(const uint32_t*)&sB[cur][nb][kb + tig * 2];
                bf[ni][1] = *(const uint32_t*)&sB[cur][nb][kb + tig * 2 + 8];
            }
#pragma unroll
            for (int mi = 0; mi < 2; mi++)
#pragma unroll
                for (int ni = 0; ni < 8; ni++) mma16816(acc[mi][ni], af[mi], bf[ni]);
        }
        if (kt + 1 < NT) { stA(cur ^ 1); stB(cur ^ 1); }
        __syncthreads();
    }

    // f16-round + f16 bias (reference numerics), widen to f32
    {
        int fl = g_flags[3];
#pragma unroll
        for (int ni = 0; ni < 8; ni++) {
            int c0 = n0 + wn * 64 + ni * 8 + tig * 2;
            __half b0 = fetch_h(biases, (size_t)lc * D + c0, (size_t)nbias, fl);
            __half b1 = fetch_h(biases, (size_t)lc * D + c0 + 1, (size_t)nbias, fl);
#pragma unroll
            for (int mi = 0; mi < 2; mi++) {
                acc[mi][ni][0] = __half2float(__hadd(__float2half(acc[mi][ni][0]), b0));
                acc[mi][ni][1] = __half2float(__hadd(__float2half(acc[mi][ni][1]), b1));
                acc[mi][ni][2] = __half2float(__hadd(__float2half(acc[mi][ni][2]), b0));
                acc[mi][ni][3] = __half2float(__hadd(__float2half(acc[mi][ni][3]), b1));
            }
        }
    }

    // LoRA as 2 extra MMA k-steps: sA[0] <- sum of t partials, sB[0] <- 0.125*Bl
#pragma unroll
    for (int i = 0; i < 16; i++) {
        int e = tid + i * 256;
        int r = e >> 5, c = e & 31;
        size_t ti = (size_t)(m0 + r) * RANK + c;
        float tv = 0.f;
#pragma unroll
        for (int p = 0; p < KSPLIT; p++) tv += g_tp[(size_t)p * MROWS * RANK + ti];
        sA[0][r][c] = __float2half(tv);
        sB[0][r][c] = __float2half(0.125f * Blbase[bloff + (size_t)(n0 + r) * RANK + c]);
    }
    __syncthreads();
#pragma unroll
    for (int kk = 0; kk < 2; kk++) {
        int kb = kk * 16;
        uint32_t af[2][4], bf[8][2];
#pragma unroll
        for (int mi = 0; mi < 2; mi++) {
            int rb = wm * 32 + mi * 16;
            af[mi][0] = *(const uint32_t*)&sA[0][rb + gid][kb + tig * 2];
            af[mi][1] = *(const uint32_t*)&sA[0][rb + gid + 8][kb + tig * 2];
            af[mi][2] = *(const uint32_t*)&sA[0][rb + gid][kb + tig * 2 + 8];
            af[mi][3] = *(const uint32_t*)&sA[0][rb + gid + 8][kb + tig * 2 + 8];
        }
#pragma unroll
        for (int ni = 0; ni < 8; ni++) {
            int nb = wn * 64 + ni * 8 + gid;
            bf[ni][0] = *(const uint32_t*)&sB[0][nb][kb + tig * 2];
            bf[ni][1] = *(const uint32_t*)&sB[0][nb][kb + tig * 2 + 8];
        }
#pragma unroll
        for (int mi = 0; mi < 2; mi++)
#pragma unroll
            for (int ni = 0; ni < 8; ni++) mma16816(acc[mi][ni], af[mi], bf[ni]);
    }

    // epilogue: residual / relu / store
#pragma unroll
    for (int mi = 0; mi < 2; mi++)
#pragma unroll
        for (int ni = 0; ni < 8; ni++) {
            int r0 = m0 + wm * 32 + mi * 16 + gid;
            int c0 = n0 + wn * 64 + ni * 8 + tig * 2;
#pragma unroll
            for (int h = 0; h < 2; h++) {
                int m = r0 + h * 8;
                float v0 = acc[mi][ni][h * 2], v1 = acc[mi][ni][h * 2 + 1];
                size_t gi = (size_t)m * D + c0;
                if (RESID) { v0 += resf32[gi]; v1 += resf32[gi + 1]; }
                if (RELU)  { v0 = fmaxf(v0, 0.f); v1 = fmaxf(v1, 0.f); }
                if (ysel == 1) {
                    g_r1h[gi] = __float2half(v0); g_r1h[gi + 1] = __float2half(v1);
                } else if (ysel == 2) {
                    g_r2h[gi] = __float2half(v0); g_r2h[gi + 1] = __float2half(v1);
                } else if ((long long)gi + 1 < nOut) {
                    out[gi] = v0; out[gi + 1] = v1;
                }
            }
        }
}

// ---------------- layernorm: in-place f32 + f16 copy for the main path ----------------
__global__ __launch_bounds__(256) void ln_kernel(float* out, long long nOut,
                                                 const float* __restrict__ gc1,
                                                 const float* __restrict__ gc2, int ng,
                                                 int blk) {
    const float* gbase = g_flags[1] ? gc2 : gc1;
    const float* bbase = g_flags[1] ? gc1 : gc2;
    int row = blockIdx.x * 8 + (threadIdx.x >> 5);
    int lane = threadIdx.x & 31;
    float v[32];
    float s = 0.f;
#pragma unroll
    for (int i = 0; i < 32; i++) {
        size_t gi = (size_t)row * D + lane + i * 32;
        v[i] = ((long long)gi < nOut) ? out[gi] : 0.f;
        s += v[i];
    }
#pragma unroll
    for (int off = 16; off > 0; off >>= 1) s += __shfl_xor_sync(0xffffffffu, s, off);
    float mu = s * (1.f / D);
    float ss = 0.f;
#pragma unroll
    for (int i = 0; i < 32; i++) { float d = v[i] - mu; ss += d * d; }
#pragma unroll
    for (int off = 16; off > 0; off >>= 1) ss += __shfl_xor_sync(0xffffffffu, ss, off);
    float inv = rsqrtf(ss * (1.f / D) + 1e-5f);
#pragma unroll
    for (int i = 0; i < 32; i++) {
        int c = lane + i * 32;
        size_t pi = (size_t)blk * D + c;
        float gg = gld(gbase, pi, (size_t)ng);
        float bb = gld(bbase, pi, (size_t)ng);
        size_t gi = (size_t)row * D + c;
        float y = (v[i] - mu) * inv * gg + bb;
        if ((long long)gi < nOut) out[gi] = y;
        g_hh[gi] = __float2half(y);
    }
}

// ---------------- host launch ----------------
extern "C" void kernel_launch(void* const* d_in, const int* in_sizes, int n_in,
                              void* d_out, int out_size) {
    float* out = (float*)d_out;

    int ix = -1, iq = -1, is_ = -1, ib = -1, iA = -1, iB = -1, ig = -1, ib2 = -1;
    for (int i = 0; i < n_in; i++) {
        int sz = in_sizes[i];
        if      (sz == 8388608)  { if (ix < 0) ix = i; }
        else if (sz == 15728640) { if (iq < 0) iq = i; }
        else if (sz == 983040)   { if (is_ < 0) is_ = i; }
        else if (sz == 15360)    { if (ib < 0) ib = i; }
        else if (sz == 491520)   { if (iA < 0) iA = i; else if (iB < 0) iB = i; }
        else if (sz == 5120)     { if (ig < 0) ig = i; else if (ib2 < 0) ib2 = i; }
    }
    bool ok = (n_in >= 8) && ix >= 0 && iq >= 0 && is_ >= 0 && ib >= 0 &&
              iA >= 0 && iB >= 0 && ig >= 0 && ib2 >= 0;
    if (!ok) {
        int mask = (ix >= 0 ? 1 : 0) | (iq >= 0 ? 2 : 0) | (is_ >= 0 ? 4 : 0) |
                   (ib >= 0 ? 8 : 0) | ((iA >= 0 && iB >= 0) ? 16 : 0) |
                   ((ig >= 0 && ib2 >= 0) ? 32 : 0);
        float val = 1.0e6f * (float)n_in + 1000.0f * (float)mask;
        long long n = out_size;
        if (n > 8388608LL) n = 8388608LL;
        diag_kernel<<<(int)((n + 255) / 256), 256>>>(out, n, val);
        return;
    }

    const float* x      = (const float*)d_in[ix];
    const int*   qw     = (const int*)d_in[iq];
    const void*  scales = d_in[is_];
    const void*  biases = d_in[ib];
    const float* lA1    = (const float*)d_in[iA];
    const float* lA2    = (const float*)d_in[iB];
    const float* lg1    = (const float*)d_in[ig];
    const float* lg2    = (const float*)d_in[ib2];
    int nx = in_sizes[ix], ns = in_sizes[is_], nb = in_sizes[ib];
    int ng = in_sizes[ig];
    long long nOut = out_size;

    probe_kernel<<<1, 32>>>(lA1, lA2, lg1, lg2, scales, biases);

    dim3 ggrid(D / BN, MROWS / BM);      // (8, 64)
    dim3 lgrid(MROWS / BM, KSPLIT);      // (64, 8)

    int li = 0;
    for (int blk = 0; blk < 6; blk++) {
        // linear 0 (+relu): h -> r1h. blk0 reads f32 x; later blocks read f16 g_hh.
        if (blk == 0) {
            lora_t_kernel<<<lgrid, 256>>>(x, -1, nx, out, lA1, lA2, li);
            gemm_kernel<0, true, false><<<ggrid, 256>>>(x, out, nOut, 1,
                                                        qw, scales, ns, biases, nb, li,
                                                        lA1, lA2, nullptr);
        } else {
            lora_t_kernel<<<lgrid, 256>>>(x, 3, nx, out, lA1, lA2, li);
            gemm_kernel<3, true, false><<<ggrid, 256>>>(nullptr, out, nOut, 1,
                                                        qw, scales, ns, biases, nb, li,
                                                        lA1, lA2, nullptr);
        }
        li++;
        // linear 1 (+relu): r1h -> r2h
        lora_t_kernel<<<lgrid, 256>>>(x, 1, nx, out, lA1, lA2, li);
        gemm_kernel<1, true, false><<<ggrid, 256>>>(nullptr, out, nOut, 2,
                                                    qw, scales, ns, biases, nb, li,
                                                    lA1, lA2, nullptr);
        li++;
        // linear 2 (+block residual): r2h -> d_out; resid = f32 stream (x or out)
        const float* hptr = (blk == 0) ? x : out;
        lora_t_kernel<<<lgrid, 256>>>(x, 2, nx, out, lA1, lA2, li);
        gemm_kernel<2, false, true><<<ggrid, 256>>>(nullptr, out, nOut, 0,
                                                    qw, scales, ns, biases, nb, li,
                                                    lA1, lA2, hptr);
        li++;
        if (blk < 5) {
            ln_kernel<<<MROWS / 8, 256>>>(out, nOut, lg1, lg2, ng, blk);
        }
    }
}